// round 15
// baseline (speedup 1.0000x reference)
#include <cuda_runtime.h>
#include <cuda_bf16.h>
#include <cstdint>
#include <cstddef>

#define BB   32
#define SS   1024
#define HH   256
#define G4   1024          // 4*H
#define WST  260           // rec w_sh row stride (floats)
#define HST  260           // rec h_sh row stride

#define HN_OFF (32ull*1024ull*512ull)            // 16777216
#define CN_OFF (HN_OFF + 2ull*32ull*512ull)      // +32768

// ---------------- device scratch (no cudaMalloc allowed) ----------------
__device__ float g_xproj[2][SS*BB][G4];           // [dir][m][gate]  268MB
__device__ float g_out0[SS*BB][512];              // layer0 output
__device__ __nv_bfloat16 g_xh[SS*BB][512];        // X hi (bf16)
__device__ __nv_bfloat16 g_xl[SS*BB][512];        // X lo (bf16)
__device__ __nv_bfloat16 g_wh[2][1024][512];      // W hi per dir
__device__ __nv_bfloat16 g_wl[2][1024][512];      // W lo per dir

// ---------------- generic helpers ---------------------------------------
__device__ __forceinline__ void fma2(unsigned long long &d,
                                     unsigned long long a,
                                     unsigned long long b) {
    asm("fma.rn.f32x2 %0, %1, %2, %0;" : "+l"(d) : "l"(a), "l"(b));
}
__device__ __forceinline__ float hsum2(unsigned long long v) {
    return __uint_as_float((unsigned)v) + __uint_as_float((unsigned)(v >> 32));
}
__device__ __forceinline__ float sigf(float x) { return 1.f / (1.f + expf(-x)); }

__device__ __forceinline__ uint32_t smem_u32(const void* p) {
    return (uint32_t)__cvta_generic_to_shared(p);
}
__device__ __forceinline__ void st_cluster_f32(uint32_t laddr, uint32_t rk, float v) {
    uint32_t ra;
    asm volatile("mapa.shared::cluster.u32 %0, %1, %2;"
                 : "=r"(ra) : "r"(laddr), "r"(rk));
    asm volatile("st.shared::cluster.f32 [%0], %1;"
                 :: "r"(ra), "f"(v) : "memory");
}
__device__ __forceinline__ uint32_t lds32(const __nv_bfloat16* p) {
    return *(const uint32_t*)p;
}
__device__ __forceinline__ void mma_bf16(float* c, const uint32_t* a,
                                         const uint32_t* b) {
    asm volatile(
        "mma.sync.aligned.m16n8k16.row.col.f32.bf16.bf16.f32 "
        "{%0,%1,%2,%3}, {%4,%5,%6,%7}, {%8,%9}, {%0,%1,%2,%3};"
        : "+f"(c[0]), "+f"(c[1]), "+f"(c[2]), "+f"(c[3])
        : "r"(a[0]), "r"(a[1]), "r"(a[2]), "r"(a[3]), "r"(b[0]), "r"(b[1]));
}

// ---------------- split kernels: fp32 -> bf16 hi/lo ----------------------
__global__ void split_x_kernel(const float* __restrict__ xin, int layer, int K) {
    const int m = blockIdx.x;
    const int k = threadIdx.x << 2;
    const float* src;
    if (layer == 0) {
        int s = m >> 5, b = m & 31;
        src = xin + ((size_t)b * SS + s) * 256 + k;
    } else {
        src = &g_out0[m][k];
    }
    float4 v = *(const float4*)src;
    float vv[4] = {v.x, v.y, v.z, v.w};
    __nv_bfloat16 hh[4], ll[4];
    #pragma unroll
    for (int i = 0; i < 4; i++) {
        hh[i] = __float2bfloat16(vv[i]);
        ll[i] = __float2bfloat16(vv[i] - __bfloat162float(hh[i]));
    }
    __nv_bfloat162 p0, p1;
    p0.x = hh[0]; p0.y = hh[1]; p1.x = hh[2]; p1.y = hh[3];
    *(__nv_bfloat162*)&g_xh[m][k]     = p0;
    *(__nv_bfloat162*)&g_xh[m][k + 2] = p1;
    p0.x = ll[0]; p0.y = ll[1]; p1.x = ll[2]; p1.y = ll[3];
    *(__nv_bfloat162*)&g_xl[m][k]     = p0;
    *(__nv_bfloat162*)&g_xl[m][k + 2] = p1;
}

__global__ void split_w_kernel(const float* __restrict__ Wf,
                               const float* __restrict__ Wb, int K) {
    const int n = blockIdx.x;
    const int dir = blockIdx.y;
    const int k = threadIdx.x << 2;
    const float* W = dir ? Wb : Wf;
    float4 v = *(const float4*)(W + (size_t)n * K + k);
    float vv[4] = {v.x, v.y, v.z, v.w};
    __nv_bfloat16 hh[4], ll[4];
    #pragma unroll
    for (int i = 0; i < 4; i++) {
        hh[i] = __float2bfloat16(vv[i]);
        ll[i] = __float2bfloat16(vv[i] - __bfloat162float(hh[i]));
    }
    __nv_bfloat162 p0, p1;
    p0.x = hh[0]; p0.y = hh[1]; p1.x = hh[2]; p1.y = hh[3];
    *(__nv_bfloat162*)&g_wh[dir][n][k]     = p0;
    *(__nv_bfloat162*)&g_wh[dir][n][k + 2] = p1;
    p0.x = ll[0]; p0.y = ll[1]; p1.x = ll[2]; p1.y = ll[3];
    *(__nv_bfloat162*)&g_wl[dir][n][k]     = p0;
    *(__nv_bfloat162*)&g_wl[dir][n][k + 2] = p1;
}

// ---------------- mma.sync xproj GEMM (R14-verbatim) ---------------------
#define KC   32
#define ASTR2 40
__global__ void __launch_bounds__(256, 2) mma_xproj_kernel(
    int NC, const float* __restrict__ bif, const float* __restrict__ bhf,
    const float* __restrict__ bib, const float* __restrict__ bhb)
{
    __shared__ __align__(16) __nv_bfloat16 smA[2][128][ASTR2];
    __shared__ __align__(16) __nv_bfloat16 smB[2][64][ASTR2];

    const int tid = threadIdx.x;
    const int wid = tid >> 5, lane = tid & 31;
    const int wm = wid & 3, wn = wid >> 2;          // warp tile coords
    const int g = lane >> 2, t = lane & 3;          // fragment coords
    const int n0 = blockIdx.x * 64, m0 = blockIdx.y * 128, dir = blockIdx.z;
    const float* bi  = dir ? bib : bif;
    const float* bhv = dir ? bhb : bhf;

    int aRow[4], aF4[4], aHL[4];
    #pragma unroll
    for (int i = 0; i < 4; i++) {
        int idx = tid + (i << 8);
        aF4[i]  = idx & 3;
        aRow[i] = (idx >> 2) & 127;
        aHL[i]  = idx >> 9;
    }
    int bRow[2], bF4[2], bHL[2];
    #pragma unroll
    for (int i = 0; i < 2; i++) {
        int idx = tid + (i << 8);
        bF4[i]  = idx & 3;
        bRow[i] = (idx >> 2) & 63;
        bHL[i]  = idx >> 8;
    }

    float acc[2][4][4];
    #pragma unroll
    for (int mt = 0; mt < 2; mt++)
        #pragma unroll
        for (int nt = 0; nt < 4; nt++)
            #pragma unroll
            for (int e = 0; e < 4; e++) acc[mt][nt][e] = 0.f;

    float4 aReg[4], bReg[2];
    #pragma unroll
    for (int i = 0; i < 4; i++)
        aReg[i] = *(const float4*)((aHL[i] ? &g_xl[0][0] : &g_xh[0][0])
                    + (size_t)(m0 + aRow[i]) * 512 + aF4[i] * 8);
    #pragma unroll
    for (int i = 0; i < 2; i++)
        bReg[i] = *(const float4*)((bHL[i] ? &g_wl[dir][0][0] : &g_wh[dir][0][0])
                    + (size_t)(n0 + bRow[i]) * 512 + bF4[i] * 8);
    #pragma unroll
    for (int i = 0; i < 4; i++)
        *(float4*)&smA[aHL[i]][aRow[i]][aF4[i] * 8] = aReg[i];
    #pragma unroll
    for (int i = 0; i < 2; i++)
        *(float4*)&smB[bHL[i]][bRow[i]][bF4[i] * 8] = bReg[i];
    __syncthreads();

    for (int c = 0; c < NC; c++) {
        const bool more = (c + 1 < NC);
        if (more) {
            const int kb = (c + 1) * KC;
            #pragma unroll
            for (int i = 0; i < 4; i++)
                aReg[i] = *(const float4*)((aHL[i] ? &g_xl[0][0] : &g_xh[0][0])
                            + (size_t)(m0 + aRow[i]) * 512 + kb + aF4[i] * 8);
            #pragma unroll
            for (int i = 0; i < 2; i++)
                bReg[i] = *(const float4*)((bHL[i] ? &g_wl[dir][0][0] : &g_wh[dir][0][0])
                            + (size_t)(n0 + bRow[i]) * 512 + kb + bF4[i] * 8);
        }
        #pragma unroll
        for (int ks = 0; ks < 2; ks++) {
            const int kk = ks * 16;
            uint32_t ah[2][4], al[2][4], bh[4][2], bl[4][2];
            #pragma unroll
            for (int mt = 0; mt < 2; mt++) {
                const int r0 = wm * 32 + mt * 16 + g;
                ah[mt][0] = lds32(&smA[0][r0    ][kk + 2*t]);
                ah[mt][1] = lds32(&smA[0][r0 + 8][kk + 2*t]);
                ah[mt][2] = lds32(&smA[0][r0    ][kk + 2*t + 8]);
                ah[mt][3] = lds32(&smA[0][r0 + 8][kk + 2*t + 8]);
                al[mt][0] = lds32(&smA[1][r0    ][kk + 2*t]);
                al[mt][1] = lds32(&smA[1][r0 + 8][kk + 2*t]);
                al[mt][2] = lds32(&smA[1][r0    ][kk + 2*t + 8]);
                al[mt][3] = lds32(&smA[1][r0 + 8][kk + 2*t + 8]);
            }
            #pragma unroll
            for (int nt = 0; nt < 4; nt++) {
                const int rn = wn * 32 + nt * 8 + g;
                bh[nt][0] = lds32(&smB[0][rn][kk + 2*t]);
                bh[nt][1] = lds32(&smB[0][rn][kk + 2*t + 8]);
                bl[nt][0] = lds32(&smB[1][rn][kk + 2*t]);
                bl[nt][1] = lds32(&smB[1][rn][kk + 2*t + 8]);
            }
            #pragma unroll
            for (int mt = 0; mt < 2; mt++)
                #pragma unroll
                for (int nt = 0; nt < 4; nt++) {
                    mma_bf16(acc[mt][nt], ah[mt], bh[nt]);
                    mma_bf16(acc[mt][nt], ah[mt], bl[nt]);
                    mma_bf16(acc[mt][nt], al[mt], bh[nt]);
                }
        }
        __syncthreads();
        if (more) {
            #pragma unroll
            for (int i = 0; i < 4; i++)
                *(float4*)&smA[aHL[i]][aRow[i]][aF4[i] * 8] = aReg[i];
            #pragma unroll
            for (int i = 0; i < 2; i++)
                *(float4*)&smB[bHL[i]][bRow[i]][bF4[i] * 8] = bReg[i];
            __syncthreads();
        }
    }

    #pragma unroll
    for (int mt = 0; mt < 2; mt++) {
        const int m = m0 + wm * 32 + mt * 16 + g;
        #pragma unroll
        for (int nt = 0; nt < 4; nt++) {
            const int n = n0 + wn * 32 + nt * 8 + 2 * t;
            const float b0 = bi[n]     + bhv[n];
            const float b1 = bi[n + 1] + bhv[n + 1];
            float2 lo, hi;
            lo.x = acc[mt][nt][0] + b0; lo.y = acc[mt][nt][1] + b1;
            hi.x = acc[mt][nt][2] + b0; hi.y = acc[mt][nt][3] + b1;
            *(float2*)&g_xproj[dir][m][n]     = lo;
            *(float2*)&g_xproj[dir][m + 8][n] = hi;
        }
    }
}

// ---------------- cluster-parallel recurrent kernel (restructured) -------
// 16 clusters x 8 CTAs, 128 threads/CTA. Thread = (jhi=warp, jl, b) computes
// ALL 4 gates over full k=256 for its (j, b): no intra-step reduction, no
// __syncthreads. Pushes h to 8 peers (DSMEM), split cluster arrive/wait
// overlapping the next-step xproj prefetch.
__global__ void __launch_bounds__(128, 1) __cluster_dims__(8, 1, 1)
rec_kernel(int layer,
           const float* __restrict__ Whf, const float* __restrict__ Whb,
           const float* __restrict__ mask, float* __restrict__ dout)
{
    extern __shared__ float sm[];
    float* w_sh   = sm;              // [128][WST]
    float* h_base = sm + 128 * WST;  // [2][4][HST]

    const int bx   = blockIdx.x;
    const int cid  = bx >> 3;
    const int rank = bx & 7;
    const int dir  = cid & 1;
    const int bg4  = (cid >> 1) * 4;
    const int tid  = threadIdx.x;
    const float* Whh = dir ? Whb : Whf;

    // persistent weight load: local row r = g*32+jl' -> Whh row g*256+rank*32+jl'
    for (int i = tid; i < 128 * 128; i += 128) {
        int r  = i >> 7;
        int kk = (i & 127) << 1;
        int g = r >> 5, jj = r & 31;
        *(float2*)&w_sh[r * WST + kk] =
            *(const float2*)&Whh[((size_t)(g * 256 + rank * 32 + jj)) * 256 + kk];
    }
    // zero h buffer 0
    for (int i = tid; i < 4 * HST; i += 128) h_base[i] = 0.f;

    // thread role: warp = jhi (0..3), lane = (b<<3)|jl
    const int wid  = tid >> 5;
    const int lane = tid & 31;
    const int jl   = lane & 7;
    const int b    = lane >> 3;
    const int jloc = wid * 8 + jl;            // 0..31
    const int jglob = rank * 32 + jloc;
    const int bglobal = bg4 + b;
    float c_reg = 0.f;

    // prefetch step-0 xproj + mask
    float xp[4]; float mt;
    {
        const int s0 = dir ? (SS - 1) : 0;
        const float* xb = &g_xproj[dir][(size_t)(s0 * 32 + bglobal)][jglob];
        #pragma unroll
        for (int g = 0; g < 4; g++) xp[g] = __ldcs(xb + g * 256);
        mt = mask[bglobal * SS + s0];
    }
    __syncthreads();

    int p = 0;
    for (int t = 0; t < SS; t++) {
        const int s = dir ? (SS - 1 - t) : t;
        const float* hb = h_base + p * 4 * HST + b * HST;

        // full-k dot for 4 gates of (jloc, b); w broadcast over b-lanes
        unsigned long long a0[4], a1[4];
        #pragma unroll
        for (int g = 0; g < 4; g++) { a0[g] = 0ull; a1[g] = 0ull; }
        const float* wr0 = &w_sh[(0 * 32 + jloc) * WST];
        const float* wr1 = &w_sh[(1 * 32 + jloc) * WST];
        const float* wr2 = &w_sh[(2 * 32 + jloc) * WST];
        const float* wr3 = &w_sh[(3 * 32 + jloc) * WST];
        #pragma unroll 8
        for (int it = 0; it < 64; it++) {
            const int kk = it * 4;
            ulonglong2 h2 = *(const ulonglong2*)&hb[kk];
            ulonglong2 w0 = *(const ulonglong2*)&wr0[kk];
            ulonglong2 w1 = *(const ulonglong2*)&wr1[kk];
            ulonglong2 w2 = *(const ulonglong2*)&wr2[kk];
            ulonglong2 w3 = *(const ulonglong2*)&wr3[kk];
            fma2(a0[0], h2.x, w0.x); fma2(a1[0], h2.y, w0.y);
            fma2(a0[1], h2.x, w1.x); fma2(a1[1], h2.y, w1.y);
            fma2(a0[2], h2.x, w2.x); fma2(a1[2], h2.y, w2.y);
            fma2(a0[3], h2.x, w3.x); fma2(a1[3], h2.y, w3.y);
        }

        // gates -> state update (all in this thread)
        float gv[4];
        #pragma unroll
        for (int g = 0; g < 4; g++)
            gv[g] = hsum2(a0[g]) + hsum2(a1[g]) + xp[g];
        float iv = sigf(gv[0]);
        float fv = sigf(gv[1]);
        float gg = tanhf(gv[2]);
        float ov = sigf(gv[3]);
        float c = (fv * c_reg + iv * gg) * mt;     // c0 = 0
        float h = ov * tanhf(c) * mt;              // h0 = 0
        c_reg = c;

        // push h into next buffer of all 8 CTAs (incl. self)
        {
            uint32_t laddr = smem_u32(h_base + (p ^ 1) * 4 * HST + b * HST + jglob);
            #pragma unroll
            for (int rk = 0; rk < 8; rk++) st_cluster_f32(laddr, rk, h);
        }

        // release pushes early; overlap prefetch with barrier latency
        if (t < SS - 1)
            asm volatile("barrier.cluster.arrive.aligned;" ::: "memory");

        // sequence outputs (fire-and-forget)
        if (layer == 0)
            g_out0[s * 32 + bglobal][dir * 256 + jglob] = h;
        else
            dout[((size_t)bglobal * SS + s) * 512 + dir * 256 + jglob] = h;
        if (t == SS - 1) {
            size_t off = (size_t)layer * BB * 512 + (size_t)bglobal * 512
                       + dir * 256 + jglob;
            dout[HN_OFF + off] = h;
            dout[CN_OFF + off] = c;
        }

        // prefetch next step's xproj + mask
        if (t + 1 < SS) {
            const int sn = dir ? (SS - 2 - t) : (t + 1);
            const float* xb = &g_xproj[dir][(size_t)(sn * 32 + bglobal)][jglob];
            #pragma unroll
            for (int g = 0; g < 4; g++) xp[g] = __ldcs(xb + g * 256);
            mt = mask[bglobal * SS + sn];
            asm volatile("barrier.cluster.wait.aligned;" ::: "memory");
        }
        p ^= 1;
    }
}

// ---------------- launch ------------------------------------------------
extern "C" void kernel_launch(void* const* d_in, const int* in_sizes, int n_in,
                              void* d_out, int out_size)
{
    const float* inputs  = (const float*)d_in[0];
    const float* mask    = (const float*)d_in[1];
    const float* l0f_Wih = (const float*)d_in[2];
    const float* l0f_Whh = (const float*)d_in[3];
    const float* l0f_bih = (const float*)d_in[4];
    const float* l0f_bhh = (const float*)d_in[5];
    const float* l0b_Wih = (const float*)d_in[6];
    const float* l0b_Whh = (const float*)d_in[7];
    const float* l0b_bih = (const float*)d_in[8];
    const float* l0b_bhh = (const float*)d_in[9];
    const float* l1f_Wih = (const float*)d_in[10];
    const float* l1f_Whh = (const float*)d_in[11];
    const float* l1f_bih = (const float*)d_in[12];
    const float* l1f_bhh = (const float*)d_in[13];
    const float* l1b_Wih = (const float*)d_in[14];
    const float* l1b_Whh = (const float*)d_in[15];
    const float* l1b_bih = (const float*)d_in[16];
    const float* l1b_bhh = (const float*)d_in[17];
    float* out = (float*)d_out;

    // rec dynamic smem: weights 128*260 + h 2*4*260 floats = 141440 B
    const int rec_shmem = (128 * WST + 8 * HST) * 4;
    cudaFuncSetAttribute(rec_kernel,
                         cudaFuncAttributeMaxDynamicSharedMemorySize, rec_shmem);

    dim3 gm(16, 256, 2);   // n-tiles, m-tiles, dirs

    // ---- layer 0 (K = 256 -> 8 chunks) ----
    split_x_kernel<<<SS * BB, 64>>>(inputs, 0, 256);
    split_w_kernel<<<dim3(1024, 2), 64>>>(l0f_Wih, l0b_Wih, 256);
    mma_xproj_kernel<<<gm, 256>>>(8, l0f_bih, l0f_bhh, l0b_bih, l0b_bhh);
    rec_kernel<<<128, 128, rec_shmem>>>(0, l0f_Whh, l0b_Whh, mask, out);

    // ---- layer 1 (K = 512 -> 16 chunks) ----
    split_x_kernel<<<SS * BB, 128>>>(nullptr, 1, 512);
    split_w_kernel<<<dim3(1024, 2), 128>>>(l1f_Wih, l1b_Wih, 512);
    mma_xproj_kernel<<<gm, 256>>>(16, l1f_bih, l1f_bhh, l1b_bih, l1b_bhh);
    rec_kernel<<<128, 128, rec_shmem>>>(1, l1f_Whh, l1b_Whh, mask, out);
}